// round 7
// baseline (speedup 1.0000x reference)
#include <cuda_runtime.h>
#include <cuda_fp16.h>
#include <cstdint>

// Problem constants
#define NB   2
#define SEQ  2048
#define DIM  1024
#define NH   16
#define HD   64
#define NW   4
#define NTOK (NB*SEQ)          // 4096
#define QKVN (3*NH*HD*NW)      // 12288
#define OUTN (DIM*NW)          // 4096

// q pre-scale: DIM_HEAD^-0.5 * log2(e)  (softmax runs in log2 domain)
#define QSCALE 0.1803368801111137f

// Scratch (device globals — no allocation allowed)
__device__ float  g_gates[NTOK * NW];
__device__ __half g_qh[NB*NH*SEQ*HD];
__device__ __half g_kh[NB*NH*SEQ*HD];
__device__ __half g_vh[NB*NH*SEQ*HD];
__device__ __half g_aoh[NTOK * DIM];
__device__ __half g_xh[NTOK * DIM];
__device__ __half g_wqkvh[DIM * QKVN];
__device__ __half g_wouth[DIM * OUTN];

__device__ __forceinline__ void cp_async16(uint32_t dst, const void* src) {
    asm volatile("cp.async.cg.shared.global [%0], [%1], 16;"
                 :: "r"(dst), "l"(src));
}
#define CP_COMMIT()  asm volatile("cp.async.commit_group;")
#define CP_WAIT(N)   asm volatile("cp.async.wait_group %0;" :: "n"(N))
__device__ __forceinline__ uint32_t smem_u32(const void* p) {
    uint32_t a;
    asm("{ .reg .u64 t; cvta.to.shared.u64 t, %1; cvt.u32.u64 %0, t; }"
        : "=r"(a) : "l"(p));
    return a;
}
__device__ __forceinline__ void ldsm4(uint32_t& r0, uint32_t& r1, uint32_t& r2,
                                      uint32_t& r3, uint32_t addr) {
    asm volatile("ldmatrix.sync.aligned.m8n8.x4.shared.b16 {%0,%1,%2,%3}, [%4];"
                 : "=r"(r0), "=r"(r1), "=r"(r2), "=r"(r3) : "r"(addr));
}
__device__ __forceinline__ void ldsm4t(uint32_t& r0, uint32_t& r1, uint32_t& r2,
                                       uint32_t& r3, uint32_t addr) {
    asm volatile("ldmatrix.sync.aligned.m8n8.x4.trans.shared.b16 {%0,%1,%2,%3}, [%4];"
                 : "=r"(r0), "=r"(r1), "=r"(r2), "=r"(r3) : "r"(addr));
}
__device__ __forceinline__ void mma_f16(float* c, uint32_t a0, uint32_t a1,
                                        uint32_t a2, uint32_t a3,
                                        uint32_t b0, uint32_t b1) {
    asm volatile(
        "mma.sync.aligned.m16n8k16.row.col.f32.f16.f16.f32 "
        "{%0,%1,%2,%3},{%4,%5,%6,%7},{%8,%9},{%0,%1,%2,%3};"
        : "+f"(c[0]), "+f"(c[1]), "+f"(c[2]), "+f"(c[3])
        : "r"(a0), "r"(a1), "r"(a2), "r"(a3), "r"(b0), "r"(b1));
}
__device__ __forceinline__ float ex2f(float x) {
    float y;
    asm("ex2.approx.ftz.f32 %0, %1;" : "=f"(y) : "f"(x));
    return y;
}
// 2^a, 2^b computed in packed fp16 (one MUFU op for two values)
__device__ __forceinline__ uint32_t ex2_h2(float a, float b) {
    __half2 h = __floats2half2_rn(a, b);
    uint32_t u = *(uint32_t*)&h;
    uint32_t r;
    asm("ex2.approx.f16x2 %0, %1;" : "=r"(r) : "r"(u));
    return r;
}

// ===========================================================================
// fp16 pre-convert (float4 -> 4 halves, grid-stride)
// ===========================================================================
__global__ void cvt_f16_kernel(__half* __restrict__ dst,
                               const float* __restrict__ src, int n4) {
    int i = blockIdx.x * blockDim.x + threadIdx.x;
    for (; i < n4; i += gridDim.x * blockDim.x) {
        float4 v = ((const float4*)src)[i];
        __half2 h0 = __floats2half2_rn(v.x, v.y);
        __half2 h1 = __floats2half2_rn(v.z, v.w);
        uint2 u;
        u.x = *(uint32_t*)&h0;
        u.y = *(uint32_t*)&h1;
        ((uint2*)dst)[i] = u;
    }
}

// ===========================================================================
// Kernel 1: gates = softmax(x @ Wg), per token (4 outputs), fp32
// ===========================================================================
__global__ void gates_kernel(const float* __restrict__ x,
                             const float* __restrict__ Wg) {
    int token = blockIdx.x;
    const float* xr = x + (size_t)token * DIM;
    __shared__ float part[128];
    int t = threadIdx.x;
    int w = t & 3, k0 = t >> 2;
    float acc = 0.f;
    for (int k = k0; k < DIM; k += 32)
        acc += xr[k] * Wg[k * NW + w];
    part[t] = acc;
    __syncthreads();
    if (t < 4) {
        float s = 0.f;
        for (int i = t; i < 128; i += 4) s += part[i];
        part[t] = s;
    }
    __syncthreads();
    if (t == 0) {
        float a0 = part[0], a1 = part[1], a2 = part[2], a3 = part[3];
        float m = fmaxf(fmaxf(a0, a1), fmaxf(a2, a3));
        float e0 = __expf(a0 - m), e1 = __expf(a1 - m);
        float e2 = __expf(a2 - m), e3 = __expf(a3 - m);
        float inv = 1.f / (e0 + e1 + e2 + e3);
        g_gates[token * 4 + 0] = e0 * inv;
        g_gates[token * 4 + 1] = e1 * inv;
        g_gates[token * 4 + 2] = e2 * inv;
        g_gates[token * 4 + 3] = e3 * inv;
    }
}

// ===========================================================================
// fp16 mma.sync GEMM: 128x128 CTA tile, 4 warps (2Mx2N) of 64x64, KC=64,
// 2-stage cp.async, ldmatrix. Gated epilogue over column groups of 4.
// MODE 0: A=g_xh, B=g_wqkvh -> scatter q/k/v (fp16, q in log2-scaled units).
// MODE 1: A=g_aoh, B=g_wouth -> out (fp32).
// ===========================================================================
#define AS_STRB 144                    // bytes per A row (64 halves + pad)
#define BS_STRB 272                    // bytes per B row (128 halves + pad)
#define A_TILE_B (128 * AS_STRB)       // 18432
#define B_TILE_B (64 * BS_STRB)        // 17408
#define OFF_GATE 0
#define OFF_A    2048
#define OFF_B    (OFF_A + 2 * A_TILE_B)
#define GEMM_SMEM (OFF_B + 2 * B_TILE_B)  // 73728
#define KC 64
#define NCHUNK (DIM / KC)              // 16

template <int MODE>
__global__ __launch_bounds__(128, 2)
void gemm_mma(const __half* __restrict__ A_, const __half* __restrict__ Bm,
              int Ncols, float* __restrict__ Cout) {
    extern __shared__ char smem[];
    float* sgate = (float*)(smem + OFF_GATE);
    const __half* A = (MODE == 1) ? (const __half*)g_aoh : A_;

    const int tid = threadIdx.x, warp = tid >> 5, lane = tid & 31;
    const int g = lane >> 2, tg = lane & 3;
    const int quad = lane >> 3, l7 = lane & 7;
    const int warpM = warp & 1, warpN = warp >> 1;
    const int bm = blockIdx.y, bn = blockIdx.x;

    const uint32_t sbase = smem_u32(smem);
    const uint32_t sA = sbase + OFF_A;
    const uint32_t sB = sbase + OFF_B;

    for (int i = tid; i < 512; i += 128)
        sgate[i] = g_gates[bm * 512 + i];

    float c[4][8][4];
#pragma unroll
    for (int mi = 0; mi < 4; mi++)
#pragma unroll
        for (int ni = 0; ni < 8; ni++)
#pragma unroll
            for (int q = 0; q < 4; q++) c[mi][ni][q] = 0.f;

    auto stageAB = [&](int kt, int st) {
        // A: 128 rows x 128B
#pragma unroll
        for (int i = 0; i < 8; i++) {
            int idx = tid + i * 128;
            int row = idx >> 3, ch = idx & 7;
            cp_async16(sA + st * A_TILE_B + row * AS_STRB + ch * 16,
                       A + (size_t)(bm * 128 + row) * DIM + kt + ch * 8);
        }
        // B: 64 k-rows x 256B
#pragma unroll
        for (int i = 0; i < 8; i++) {
            int idx = tid + i * 128;
            int row = idx >> 4, ch = idx & 15;
            cp_async16(sB + st * B_TILE_B + row * BS_STRB + ch * 16,
                       Bm + (size_t)(kt + row) * Ncols + bn * 128 + ch * 8);
        }
    };

    stageAB(0, 0);
    CP_COMMIT();

    for (int ch = 0; ch < NCHUNK; ch++) {
        CP_WAIT(0);
        __syncthreads();
        if (ch + 1 < NCHUNK) {
            stageAB((ch + 1) * KC, (ch + 1) & 1);
            CP_COMMIT();
        }
        const int cur = ch & 1;
        const uint32_t sAc = sA + cur * A_TILE_B;
        const uint32_t sBc = sB + cur * B_TILE_B;
#pragma unroll
        for (int ks = 0; ks < 4; ks++) {
            uint32_t bf[8][2];
#pragma unroll
            for (int p = 0; p < 4; p++) {
                int krow = ks * 16 + l7 + (quad & 1) * 8;
                int ncol = warpN * 64 + p * 16 + (quad >> 1) * 8;
                uint32_t r0, r1, r2, r3;
                ldsm4t(r0, r1, r2, r3, sBc + krow * BS_STRB + ncol * 2);
                bf[2*p][0] = r0; bf[2*p][1] = r1;
                bf[2*p+1][0] = r2; bf[2*p+1][1] = r3;
            }
#pragma unroll
            for (int mi = 0; mi < 4; mi++) {
                int arow = warpM * 64 + mi * 16 + l7 + (quad & 1) * 8;
                uint32_t a0, a1, a2, a3;
                ldsm4(a0, a1, a2, a3,
                      sAc + arow * AS_STRB + ks * 32 + (quad >> 1) * 16);
#pragma unroll
                for (int ni = 0; ni < 8; ni++)
                    mma_f16(c[mi][ni], a0, a1, a2, a3, bf[ni][0], bf[ni][1]);
            }
        }
    }

    // --- gated epilogue ---
    const int w0 = (2 * tg) & 3;  // 0 or 2
#pragma unroll
    for (int mi = 0; mi < 4; mi++) {
        int r0 = warpM * 64 + mi * 16 + g;
        float2 ga = *(float2*)&sgate[r0 * 4 + w0];
        float2 gb = *(float2*)&sgate[(r0 + 8) * 4 + w0];
#pragma unroll
        for (int ni = 0; ni < 8; ni++) {
            float p01 = c[mi][ni][0] * ga.x + c[mi][ni][1] * ga.y;
            float p23 = c[mi][ni][2] * gb.x + c[mi][ni][3] * gb.y;
            p01 += __shfl_xor_sync(0xffffffffu, p01, 1);
            p23 += __shfl_xor_sync(0xffffffffu, p23, 1);
            if ((tg & 1) == 0) {
                int grp = bn * 32 + warpN * 16 + ni * 2 + (tg >> 1);
                int tok0 = bm * 128 + r0;
#pragma unroll
                for (int rr = 0; rr < 2; rr++) {
                    int token = tok0 + rr * 8;
                    float v = rr ? p23 : p01;
                    if (MODE == 0) {
                        int qkv = grp >> 10, rem = grp & 1023;
                        int h = rem >> 6, d = rem & 63;
                        int b = token >> 11, n = token & 2047;
                        size_t idx = (((size_t)(b * NH + h)) * SEQ + n) * HD + d;
                        if (qkv == 0)      g_qh[idx] = __float2half_rn(v * QSCALE);
                        else if (qkv == 1) g_kh[idx] = __float2half_rn(v);
                        else               g_vh[idx] = __float2half_rn(v);
                    } else {
                        Cout[(size_t)token * DIM + grp] = v;
                    }
                }
            }
        }
    }
}

// ===========================================================================
// Kernel 3: fp16 flash attention, log2-domain softmax, P stays in registers
// (S C-frag pairs == PV A-frags). Block = 128 q rows, 4 warps x 32 rows.
// KV tiles of 64, 2-stage cp.async. occ 2.
// ===========================================================================
#define TSTRB 144
#define KV_TILE_B (64 * TSTRB)          // 9216
#define AOFF_K 0
#define AOFF_V (2 * KV_TILE_B)          // 18432
#define AOFF_Q (4 * KV_TILE_B)          // 36864
#define ATT_SMEM (AOFF_Q + 128 * TSTRB) // 55296
#define NKT (SEQ / 64)

__global__ __launch_bounds__(128, 2)
void attn_tc() {
    extern __shared__ char smem[];
    const uint32_t sbase = smem_u32(smem);
    const uint32_t sK = sbase + AOFF_K, sV = sbase + AOFF_V;
    const uint32_t sQ = sbase + AOFF_Q;

    const int tid = threadIdx.x, warp = tid >> 5, lane = tid & 31;
    const int g = lane >> 2, tg = lane & 3;
    const int quad = lane >> 3, l7 = lane & 7;
    const int qt = blockIdx.x, bh = blockIdx.y;
    const int b = bh >> 4, h = bh & 15;

    const __half* Qb = g_qh + ((size_t)bh * SEQ + qt * 128) * HD;
    const __half* Kb = g_kh + (size_t)bh * SEQ * HD;
    const __half* Vb = g_vh + (size_t)bh * SEQ * HD;

    auto stageKV = [&](int kt, int st) {
        const __half* Ksrc = Kb + (size_t)kt * 64 * HD;
        const __half* Vsrc = Vb + (size_t)kt * 64 * HD;
#pragma unroll
        for (int i = 0; i < 4; i++) {
            int idx = tid + i * 128;        // 512 chunks each
            int row = idx >> 3, ch = idx & 7;
            cp_async16(sK + st * KV_TILE_B + row * TSTRB + ch * 16,
                       Ksrc + (size_t)row * HD + ch * 8);
            cp_async16(sV + st * KV_TILE_B + row * TSTRB + ch * 16,
                       Vsrc + (size_t)row * HD + ch * 8);
        }
    };

    stageKV(0, 0);
    CP_COMMIT();

    // Stage Q (128 rows x 128B), extract persistent fragments.
#pragma unroll
    for (int i = 0; i < 8; i++) {
        int idx = tid + i * 128;
        int row = idx >> 3, ch = idx & 7;
        *(uint4*)(smem + AOFF_Q + row * TSTRB + ch * 16) =
            *(const uint4*)(Qb + (size_t)row * HD + ch * 8);
    }
    __syncthreads();

    uint32_t qf[4][2][4];
#pragma unroll
    for (int mi = 0; mi < 2; mi++) {
        int qrow = warp * 32 + mi * 16 + l7 + (quad & 1) * 8;
#pragma unroll
        for (int kc = 0; kc < 4; kc++)
            ldsm4(qf[kc][mi][0], qf[kc][mi][1], qf[kc][mi][2], qf[kc][mi][3],
                  sQ + qrow * TSTRB + kc * 32 + (quad >> 1) * 16);
    }

    float o[2][8][4];
#pragma unroll
    for (int mi = 0; mi < 2; mi++)
#pragma unroll
        for (int ni = 0; ni < 8; ni++)
#pragma unroll
            for (int q = 0; q < 4; q++) o[mi][ni][q] = 0.f;
    float m[2][2] = {{-1e30f, -1e30f}, {-1e30f, -1e30f}};
    float l[2][2] = {{0.f, 0.f}, {0.f, 0.f}};

    for (int kt = 0; kt < NKT; kt++) {
        CP_WAIT(0);
        __syncthreads();
        if (kt + 1 < NKT) {
            stageKV(kt + 1, (kt + 1) & 1);
            CP_COMMIT();
        }
        const int cur = kt & 1;
        const uint32_t sKc = sK + cur * KV_TILE_B;
        const uint32_t sVc = sV + cur * KV_TILE_B;

        // S = Q K^T  (32 x 64 per warp, in log2 units — q pre-scaled)
        float s[2][8][4];
#pragma unroll
        for (int mi = 0; mi < 2; mi++)
#pragma unroll
            for (int ni = 0; ni < 8; ni++)
#pragma unroll
                for (int q = 0; q < 4; q++) s[mi][ni][q] = 0.f;
#pragma unroll
        for (int kc = 0; kc < 4; kc++) {
#pragma unroll
            for (int p = 0; p < 4; p++) {
                int nrow = p * 16 + l7 + (quad >> 1) * 8;
                uint32_t r0, r1, r2, r3;
                ldsm4(r0, r1, r2, r3,
                      sKc + nrow * TSTRB + kc * 32 + (quad & 1) * 16);
#pragma unroll
                for (int mi = 0; mi < 2; mi++) {
                    mma_f16(s[mi][2*p],   qf[kc][mi][0], qf[kc][mi][1],
                            qf[kc][mi][2], qf[kc][mi][3], r0, r1);
                    mma_f16(s[mi][2*p+1], qf[kc][mi][0], qf[kc][mi][1],
                            qf[kc][mi][2], qf[kc][mi][3], r2, r3);
                }
            }
        }

        // Online softmax in log2 domain; P packed fp16 == PV A-fragments.
        uint32_t ph[2][8][2];
#pragma unroll
        for (int mi = 0; mi < 2; mi++) {
            float tm0 = -1e30f, tm1 = -1e30f;
#pragma unroll
            for (int ni = 0; ni < 8; ni++) {
                tm0 = fmaxf(tm0, fmaxf(s[mi][ni][0], s[mi][ni][1]));
                tm1 = fmaxf(tm1, fmaxf(s[mi][ni][2], s[mi][ni][3]));
            }
#pragma unroll
            for (int msk = 1; msk <= 2; msk <<= 1) {
                tm0 = fmaxf(tm0, __shfl_xor_sync(0xffffffffu, tm0, msk));
                tm1 = fmaxf(tm1, __shfl_xor_sync(0xffffffffu, tm1, msk));
            }
            float mn0 = fmaxf(m[mi][0], tm0), mn1 = fmaxf(m[mi][1], tm1);
            float al0 = ex2f(m[mi][0] - mn0), al1 = ex2f(m[mi][1] - mn1);
            float sum0 = 0.f, sum1 = 0.f;
#pragma unroll
            for (int ni = 0; ni < 8; ni++) {
                ph[mi][ni][0] = ex2_h2(s[mi][ni][0] - mn0, s[mi][ni][1] - mn0);
                ph[mi][ni][1] = ex2_h2(s[mi][ni][2] - mn1, s[mi][ni][3] - mn1);
                float2 f0 = __half22float2(*(__half2*)&ph[mi][ni][0]);
                float2 f1 = __half22float2(*(__half2*)&ph[mi][ni][1]);
                sum0 += f0.x + f0.y;
                sum1 += f1.x + f1.y;
            }
#pragma unroll
            for (int msk = 1; msk <= 2; msk <<= 1) {
                sum0 += __shfl_xor_sync(0xffffffffu, sum0, msk);
                sum1 += __shfl_xor_sync(0xffffffffu, sum1, msk);
            }
            l[mi][0] = l[mi][0] * al0 + sum0;
            l[mi][1] = l[mi][1] * al1 + sum1;
            m[mi][0] = mn0; m[mi][1] = mn1;
#pragma unroll
            for (int ni = 0; ni < 8; ni++) {
                o[mi][ni][0] *= al0; o[mi][ni][1] *= al0;
                o[mi][ni][2] *= al1; o[mi][ni][3] *= al1;
            }
        }

        // O += P V  (P A-frags straight from registers)
#pragma unroll
        for (int kc = 0; kc < 4; kc++) {
#pragma unroll
            for (int p = 0; p < 4; p++) {
                int krow = kc * 16 + l7 + (quad & 1) * 8;
                int ncol = p * 16 + (quad >> 1) * 8;
                uint32_t r0, r1, r2, r3;
                ldsm4t(r0, r1, r2, r3, sVc + krow * TSTRB + ncol * 2);
#pragma unroll
                for (int mi = 0; mi < 2; mi++) {
                    mma_f16(o[mi][2*p],   ph[mi][2*kc][0], ph[mi][2*kc][1],
                            ph[mi][2*kc+1][0], ph[mi][2*kc+1][1], r0, r1);
                    mma_f16(o[mi][2*p+1], ph[mi][2*kc][0], ph[mi][2*kc][1],
                            ph[mi][2*kc+1][0], ph[mi][2*kc+1][1], r2, r3);
                }
            }
        }
    }

    // Write ao (fp16 for gemm1)
#pragma unroll
    for (int mi = 0; mi < 2; mi++) {
        float inv0 = 1.f / l[mi][0], inv1 = 1.f / l[mi][1];
        int tok0 = b * SEQ + qt * 128 + warp * 32 + mi * 16 + g;
#pragma unroll
        for (int ni = 0; ni < 8; ni++) {
            int col = h * HD + ni * 8 + 2 * tg;
            *(__half2*)&g_aoh[(size_t)tok0 * DIM + col] =
                __floats2half2_rn(o[mi][ni][0] * inv0, o[mi][ni][1] * inv0);
            *(__half2*)&g_aoh[(size_t)(tok0 + 8) * DIM + col] =
                __floats2half2_rn(o[mi][ni][2] * inv1, o[mi][ni][3] * inv1);
        }
    }
}

// ===========================================================================
extern "C" void kernel_launch(void* const* d_in, const int* in_sizes, int n_in,
                              void* d_out, int out_size) {
    const float* x    = (const float*)d_in[0];
    const float* Wqkv = (const float*)d_in[1];
    const float* Wg   = (const float*)d_in[2];
    const float* Wout = (const float*)d_in[3];
    // d_in[4] = mask: all-true by construction, unused.
    float* out = (float*)d_out;

    cudaFuncSetAttribute(gemm_mma<0>, cudaFuncAttributeMaxDynamicSharedMemorySize, GEMM_SMEM);
    cudaFuncSetAttribute(gemm_mma<1>, cudaFuncAttributeMaxDynamicSharedMemorySize, GEMM_SMEM);
    cudaFuncSetAttribute(attn_tc, cudaFuncAttributeMaxDynamicSharedMemorySize, ATT_SMEM);

    __half* xh; __half* wqkvh; __half* wouth;
    cudaGetSymbolAddress((void**)&xh, g_xh);
    cudaGetSymbolAddress((void**)&wqkvh, g_wqkvh);
    cudaGetSymbolAddress((void**)&wouth, g_wouth);

    cvt_f16_kernel<<<2048, 256>>>(xh, x, NTOK * DIM / 4);
    cvt_f16_kernel<<<4096, 256>>>(wqkvh, Wqkv, DIM * QKVN / 4);
    cvt_f16_kernel<<<2048, 256>>>(wouth, Wout, DIM * OUTN / 4);
    gates_kernel<<<NTOK, 128>>>(x, Wg);
    gemm_mma<0><<<dim3(QKVN / 128, NTOK / 128), 128, GEMM_SMEM>>>(xh, wqkvh, QKVN, nullptr);
    attn_tc<<<dim3(SEQ / 128, NB * NH), 128, ATT_SMEM>>>();
    gemm_mma<1><<<dim3(OUTN / 128, NTOK / 128), 128, GEMM_SMEM>>>(nullptr, wouth, OUTN, out);
}

// round 8
// speedup vs baseline: 1.0491x; 1.0491x over previous
#include <cuda_runtime.h>
#include <cuda_fp16.h>
#include <cstdint>

// Problem constants
#define NB   2
#define SEQ  2048
#define DIM  1024
#define NH   16
#define HD   64
#define NW   4
#define NTOK (NB*SEQ)          // 4096
#define QKVN (3*NH*HD*NW)      // 12288
#define OUTN (DIM*NW)          // 4096

// q pre-scale: DIM_HEAD^-0.5 * log2(e)  (softmax runs in log2 domain)
#define QSCALE 0.1803368801111137f

// Scratch (device globals — no allocation allowed)
__device__ float  g_gates[NTOK * NW];
__device__ __half g_qh[NB*NH*SEQ*HD];
__device__ __half g_kh[NB*NH*SEQ*HD];
__device__ __half g_vh[NB*NH*SEQ*HD];
__device__ __half g_aoh[NTOK * DIM];
__device__ __half g_xh[NTOK * DIM];
__device__ __half g_wqkvh[DIM * QKVN];
__device__ __half g_wouth[DIM * OUTN];

__device__ __forceinline__ void cp_async16(uint32_t dst, const void* src) {
    asm volatile("cp.async.cg.shared.global [%0], [%1], 16;"
                 :: "r"(dst), "l"(src));
}
#define CP_COMMIT()  asm volatile("cp.async.commit_group;")
#define CP_WAIT(N)   asm volatile("cp.async.wait_group %0;" :: "n"(N))
__device__ __forceinline__ uint32_t smem_u32(const void* p) {
    uint32_t a;
    asm("{ .reg .u64 t; cvta.to.shared.u64 t, %1; cvt.u32.u64 %0, t; }"
        : "=r"(a) : "l"(p));
    return a;
}
__device__ __forceinline__ void ldsm4(uint32_t& r0, uint32_t& r1, uint32_t& r2,
                                      uint32_t& r3, uint32_t addr) {
    asm volatile("ldmatrix.sync.aligned.m8n8.x4.shared.b16 {%0,%1,%2,%3}, [%4];"
                 : "=r"(r0), "=r"(r1), "=r"(r2), "=r"(r3) : "r"(addr));
}
__device__ __forceinline__ void ldsm4t(uint32_t& r0, uint32_t& r1, uint32_t& r2,
                                       uint32_t& r3, uint32_t addr) {
    asm volatile("ldmatrix.sync.aligned.m8n8.x4.trans.shared.b16 {%0,%1,%2,%3}, [%4];"
                 : "=r"(r0), "=r"(r1), "=r"(r2), "=r"(r3) : "r"(addr));
}
__device__ __forceinline__ void mma_f16(float* c, uint32_t a0, uint32_t a1,
                                        uint32_t a2, uint32_t a3,
                                        uint32_t b0, uint32_t b1) {
    asm volatile(
        "mma.sync.aligned.m16n8k16.row.col.f32.f16.f16.f32 "
        "{%0,%1,%2,%3},{%4,%5,%6,%7},{%8,%9},{%0,%1,%2,%3};"
        : "+f"(c[0]), "+f"(c[1]), "+f"(c[2]), "+f"(c[3])
        : "r"(a0), "r"(a1), "r"(a2), "r"(a3), "r"(b0), "r"(b1));
}
__device__ __forceinline__ float ex2f(float x) {
    float y;
    asm("ex2.approx.ftz.f32 %0, %1;" : "=f"(y) : "f"(x));
    return y;
}
__device__ __forceinline__ uint32_t ex2_h2(float a, float b) {
    __half2 h = __floats2half2_rn(a, b);
    uint32_t u = *(uint32_t*)&h;
    uint32_t r;
    asm("ex2.approx.f16x2 %0, %1;" : "=r"(r) : "r"(u));
    return r;
}

// ===========================================================================
// Fused fp16 pre-convert for x, Wqkv, Wout (one launch, grid-stride)
// ===========================================================================
#define NX4  (NTOK * DIM / 4)
#define NWQ4 (DIM * QKVN / 4)
#define NWO4 (DIM * OUTN / 4)
__global__ void cvt_all_kernel(const float* __restrict__ x,
                               const float* __restrict__ wqkv,
                               const float* __restrict__ wout) {
    int i = blockIdx.x * blockDim.x + threadIdx.x;
    const int total = NX4 + NWQ4 + NWO4;
    for (; i < total; i += gridDim.x * blockDim.x) {
        float4 v;
        if (i < NX4)                v = ((const float4*)x)[i];
        else if (i < NX4 + NWQ4)    v = ((const float4*)wqkv)[i - NX4];
        else                        v = ((const float4*)wout)[i - NX4 - NWQ4];
        __half2 h0 = __floats2half2_rn(v.x, v.y);
        __half2 h1 = __floats2half2_rn(v.z, v.w);
        uint2 u;
        u.x = *(uint32_t*)&h0;
        u.y = *(uint32_t*)&h1;
        if (i < NX4)                ((uint2*)g_xh)[i] = u;
        else if (i < NX4 + NWQ4)    ((uint2*)g_wqkvh)[i - NX4] = u;
        else                        ((uint2*)g_wouth)[i - NX4 - NWQ4] = u;
    }
}

// ===========================================================================
// Kernel 1: gates = softmax(x @ Wg), per token (4 outputs), fp32
// ===========================================================================
__global__ void gates_kernel(const float* __restrict__ x,
                             const float* __restrict__ Wg) {
    int token = blockIdx.x;
    const float* xr = x + (size_t)token * DIM;
    __shared__ float part[128];
    int t = threadIdx.x;
    int w = t & 3, k0 = t >> 2;
    float acc = 0.f;
    for (int k = k0; k < DIM; k += 32)
        acc += xr[k] * Wg[k * NW + w];
    part[t] = acc;
    __syncthreads();
    if (t < 4) {
        float s = 0.f;
        for (int i = t; i < 128; i += 4) s += part[i];
        part[t] = s;
    }
    __syncthreads();
    if (t == 0) {
        float a0 = part[0], a1 = part[1], a2 = part[2], a3 = part[3];
        float m = fmaxf(fmaxf(a0, a1), fmaxf(a2, a3));
        float e0 = __expf(a0 - m), e1 = __expf(a1 - m);
        float e2 = __expf(a2 - m), e3 = __expf(a3 - m);
        float inv = 1.f / (e0 + e1 + e2 + e3);
        g_gates[token * 4 + 0] = e0 * inv;
        g_gates[token * 4 + 1] = e1 * inv;
        g_gates[token * 4 + 2] = e2 * inv;
        g_gates[token * 4 + 3] = e3 * inv;
    }
}

// ===========================================================================
// fp16 mma.sync GEMM (R6 config): 128x128 CTA tile, KC=64, 2-stage cp.async,
// 8 warps = 2(M) x 4(N), warp tile 64x32. Gated epilogue.
// MODE 0: A=g_xh, B=g_wqkvh -> q/k/v (q in log2-scaled units).
// MODE 1: A=g_aoh, B=g_wouth -> out (fp32).
// ===========================================================================
#define AS_STRB 144
#define BS_STRB 272
#define A_TILE_B (128 * AS_STRB)       // 18432
#define B_TILE_B (64 * BS_STRB)        // 17408
#define OFF_GATE 0
#define OFF_A    2048
#define OFF_B    (OFF_A + 2 * A_TILE_B)
#define GEMM_SMEM (OFF_B + 2 * B_TILE_B)  // 73728
#define KC 64
#define NCHUNK (DIM / KC)              // 16

template <int MODE>
__global__ __launch_bounds__(256, 2)
void gemm_mma(int Ncols, float* __restrict__ Cout) {
    extern __shared__ char smem[];
    float* sgate = (float*)(smem + OFF_GATE);
    const __half* A = (MODE == 1) ? (const __half*)g_aoh : (const __half*)g_xh;
    const __half* Bm = (MODE == 1) ? (const __half*)g_wouth : (const __half*)g_wqkvh;

    const int tid = threadIdx.x, warp = tid >> 5, lane = tid & 31;
    const int g = lane >> 2, tg = lane & 3;
    const int quad = lane >> 3, l7 = lane & 7;
    const int warpM = warp >> 2, warpN = warp & 3;
    const int bm = blockIdx.y, bn = blockIdx.x;

    const uint32_t sbase = smem_u32(smem);
    const uint32_t sA = sbase + OFF_A;
    const uint32_t sB = sbase + OFF_B;

    for (int i = tid; i < 512; i += 256)
        sgate[i] = g_gates[bm * 512 + i];

    float c[4][4][4];
#pragma unroll
    for (int mi = 0; mi < 4; mi++)
#pragma unroll
        for (int ni = 0; ni < 4; ni++)
#pragma unroll
            for (int q = 0; q < 4; q++) c[mi][ni][q] = 0.f;

    auto stageAB = [&](int kt, int st) {
#pragma unroll
        for (int i = 0; i < 4; i++) {
            int idx = tid + i * 256;
            int row = idx >> 3, ch = idx & 7;
            cp_async16(sA + st * A_TILE_B + row * AS_STRB + ch * 16,
                       A + (size_t)(bm * 128 + row) * DIM + kt + ch * 8);
        }
#pragma unroll
        for (int i = 0; i < 4; i++) {
            int idx = tid + i * 256;
            int row = idx >> 4, ch = idx & 15;
            cp_async16(sB + st * B_TILE_B + row * BS_STRB + ch * 16,
                       Bm + (size_t)(kt + row) * Ncols + bn * 128 + ch * 8);
        }
    };

    stageAB(0, 0);
    CP_COMMIT();

    for (int ch = 0; ch < NCHUNK; ch++) {
        CP_WAIT(0);
        __syncthreads();
        if (ch + 1 < NCHUNK) {
            stageAB((ch + 1) * KC, (ch + 1) & 1);
            CP_COMMIT();
        }
        const int cur = ch & 1;
        const uint32_t sAc = sA + cur * A_TILE_B;
        const uint32_t sBc = sB + cur * B_TILE_B;
#pragma unroll
        for (int ks = 0; ks < 4; ks++) {
            uint32_t bf[4][2];
#pragma unroll
            for (int p = 0; p < 2; p++) {
                int krow = ks * 16 + l7 + (quad & 1) * 8;
                int ncol = warpN * 32 + p * 16 + (quad >> 1) * 8;
                uint32_t r0, r1, r2, r3;
                ldsm4t(r0, r1, r2, r3, sBc + krow * BS_STRB + ncol * 2);
                bf[2*p][0] = r0; bf[2*p][1] = r1;
                bf[2*p+1][0] = r2; bf[2*p+1][1] = r3;
            }
#pragma unroll
            for (int mi = 0; mi < 4; mi++) {
                int arow = warpM * 64 + mi * 16 + l7 + (quad & 1) * 8;
                uint32_t a0, a1, a2, a3;
                ldsm4(a0, a1, a2, a3,
                      sAc + arow * AS_STRB + ks * 32 + (quad >> 1) * 16);
#pragma unroll
                for (int ni = 0; ni < 4; ni++)
                    mma_f16(c[mi][ni], a0, a1, a2, a3, bf[ni][0], bf[ni][1]);
            }
        }
    }
    __syncthreads();

    // --- gated epilogue ---
    const int w0 = (2 * tg) & 3;  // 0 or 2
#pragma unroll
    for (int mi = 0; mi < 4; mi++) {
        int r0 = warpM * 64 + mi * 16 + g;
        float2 ga = *(float2*)&sgate[r0 * 4 + w0];
        float2 gb = *(float2*)&sgate[(r0 + 8) * 4 + w0];
#pragma unroll
        for (int ni = 0; ni < 4; ni++) {
            float p01 = c[mi][ni][0] * ga.x + c[mi][ni][1] * ga.y;
            float p23 = c[mi][ni][2] * gb.x + c[mi][ni][3] * gb.y;
            p01 += __shfl_xor_sync(0xffffffffu, p01, 1);
            p23 += __shfl_xor_sync(0xffffffffu, p23, 1);
            if ((tg & 1) == 0) {
                int grp = bn * 32 + warpN * 8 + ni * 2 + (tg >> 1);
                int tok0 = bm * 128 + r0;
#pragma unroll
                for (int rr = 0; rr < 2; rr++) {
                    int token = tok0 + rr * 8;
                    float v = rr ? p23 : p01;
                    if (MODE == 0) {
                        int qkv = grp >> 10, rem = grp & 1023;
                        int h = rem >> 6, d = rem & 63;
                        int b = token >> 11, n = token & 2047;
                        size_t idx = (((size_t)(b * NH + h)) * SEQ + n) * HD + d;
                        if (qkv == 0)      g_qh[idx] = __float2half_rn(v * QSCALE);
                        else if (qkv == 1) g_kh[idx] = __float2half_rn(v);
                        else               g_vh[idx] = __float2half_rn(v);
                    } else {
                        Cout[(size_t)token * DIM + grp] = v;
                    }
                }
            }
        }
    }
}

// ===========================================================================
// Kernel 3: fp16 flash attention. 256 threads, 8 warps x 16 q-rows (128 per
// CTA), log2-domain softmax (q pre-scaled), P in registers (S C-frag pairs
// == PV A-frags), KV tiles of 64, 2-stage cp.async. occ 2.
// ===========================================================================
#define TSTRB 144
#define KV_TILE_B (64 * TSTRB)          // 9216
#define AOFF_K 0
#define AOFF_V (2 * KV_TILE_B)          // 18432
#define AOFF_Q (4 * KV_TILE_B)          // 36864
#define ATT_SMEM (AOFF_Q + 128 * TSTRB) // 55296
#define NKT (SEQ / 64)

__global__ __launch_bounds__(256, 2)
void attn_tc() {
    extern __shared__ char smem[];
    const uint32_t sbase = smem_u32(smem);
    const uint32_t sK = sbase + AOFF_K, sV = sbase + AOFF_V;
    const uint32_t sQ = sbase + AOFF_Q;

    const int tid = threadIdx.x, warp = tid >> 5, lane = tid & 31;
    const int g = lane >> 2, tg = lane & 3;
    const int quad = lane >> 3, l7 = lane & 7;
    const int qt = blockIdx.x, bh = blockIdx.y;
    const int b = bh >> 4, h = bh & 15;

    const __half* Qb = g_qh + ((size_t)bh * SEQ + qt * 128) * HD;
    const __half* Kb = g_kh + (size_t)bh * SEQ * HD;
    const __half* Vb = g_vh + (size_t)bh * SEQ * HD;

    auto stageKV = [&](int kt, int st) {
        const __half* Ksrc = Kb + (size_t)kt * 64 * HD;
        const __half* Vsrc = Vb + (size_t)kt * 64 * HD;
#pragma unroll
        for (int i = 0; i < 2; i++) {
            int idx = tid + i * 256;        // 512 chunks each
            int row = idx >> 3, ch = idx & 7;
            cp_async16(sK + st * KV_TILE_B + row * TSTRB + ch * 16,
                       Ksrc + (size_t)row * HD + ch * 8);
            cp_async16(sV + st * KV_TILE_B + row * TSTRB + ch * 16,
                       Vsrc + (size_t)row * HD + ch * 8);
        }
    };

    stageKV(0, 0);
    CP_COMMIT();

    // Stage Q (128 rows x 128B), extract persistent fragments.
#pragma unroll
    for (int i = 0; i < 4; i++) {
        int idx = tid + i * 256;
        int row = idx >> 3, ch = idx & 7;
        *(uint4*)(smem + AOFF_Q + row * TSTRB + ch * 16) =
            *(const uint4*)(Qb + (size_t)row * HD + ch * 8);
    }
    __syncthreads();

    uint32_t qf[4][4];
    {
        int qrow = warp * 16 + l7 + (quad & 1) * 8;
#pragma unroll
        for (int kc = 0; kc < 4; kc++)
            ldsm4(qf[kc][0], qf[kc][1], qf[kc][2], qf[kc][3],
                  sQ + qrow * TSTRB + kc * 32 + (quad >> 1) * 16);
    }

    float o[8][4];
#pragma unroll
    for (int ni = 0; ni < 8; ni++)
#pragma unroll
        for (int q = 0; q < 4; q++) o[ni][q] = 0.f;
    float m0 = -1e30f, m1 = -1e30f, l0 = 0.f, l1 = 0.f;

    for (int kt = 0; kt < NKT; kt++) {
        CP_WAIT(0);
        __syncthreads();
        if (kt + 1 < NKT) {
            stageKV(kt + 1, (kt + 1) & 1);
            CP_COMMIT();
        }
        const int cur = kt & 1;
        const uint32_t sKc = sK + cur * KV_TILE_B;
        const uint32_t sVc = sV + cur * KV_TILE_B;

        // S = Q K^T  (16 x 64 per warp, log2 units)
        float s[8][4];
#pragma unroll
        for (int ni = 0; ni < 8; ni++)
#pragma unroll
            for (int q = 0; q < 4; q++) s[ni][q] = 0.f;
#pragma unroll
        for (int kc = 0; kc < 4; kc++) {
#pragma unroll
            for (int p = 0; p < 4; p++) {
                int nrow = p * 16 + l7 + (quad >> 1) * 8;
                uint32_t r0, r1, r2, r3;
                ldsm4(r0, r1, r2, r3,
                      sKc + nrow * TSTRB + kc * 32 + (quad & 1) * 16);
                mma_f16(s[2*p],   qf[kc][0], qf[kc][1], qf[kc][2], qf[kc][3], r0, r1);
                mma_f16(s[2*p+1], qf[kc][0], qf[kc][1], qf[kc][2], qf[kc][3], r2, r3);
            }
        }

        // Online softmax in log2 domain; P packed fp16 == PV A-fragments.
        uint32_t ph[8][2];
        {
            float tm0 = -1e30f, tm1 = -1e30f;
#pragma unroll
            for (int ni = 0; ni < 8; ni++) {
                tm0 = fmaxf(tm0, fmaxf(s[ni][0], s[ni][1]));
                tm1 = fmaxf(tm1, fmaxf(s[ni][2], s[ni][3]));
            }
#pragma unroll
            for (int msk = 1; msk <= 2; msk <<= 1) {
                tm0 = fmaxf(tm0, __shfl_xor_sync(0xffffffffu, tm0, msk));
                tm1 = fmaxf(tm1, __shfl_xor_sync(0xffffffffu, tm1, msk));
            }
            float mn0 = fmaxf(m0, tm0), mn1 = fmaxf(m1, tm1);
            float al0 = ex2f(m0 - mn0), al1 = ex2f(m1 - mn1);
            float sum0 = 0.f, sum1 = 0.f;
#pragma unroll
            for (int ni = 0; ni < 8; ni++) {
                ph[ni][0] = ex2_h2(s[ni][0] - mn0, s[ni][1] - mn0);
                ph[ni][1] = ex2_h2(s[ni][2] - mn1, s[ni][3] - mn1);
                float2 f0 = __half22float2(*(__half2*)&ph[ni][0]);
                float2 f1 = __half22float2(*(__half2*)&ph[ni][1]);
                sum0 += f0.x + f0.y;
                sum1 += f1.x + f1.y;
            }
#pragma unroll
            for (int msk = 1; msk <= 2; msk <<= 1) {
                sum0 += __shfl_xor_sync(0xffffffffu, sum0, msk);
                sum1 += __shfl_xor_sync(0xffffffffu, sum1, msk);
            }
            l0 = l0 * al0 + sum0;
            l1 = l1 * al1 + sum1;
            m0 = mn0; m1 = mn1;
#pragma unroll
            for (int ni = 0; ni < 8; ni++) {
                o[ni][0] *= al0; o[ni][1] *= al0;
                o[ni][2] *= al1; o[ni][3] *= al1;
            }
        }

        // O += P V  (P A-frags straight from registers)
#pragma unroll
        for (int kc = 0; kc < 4; kc++) {
#pragma unroll
            for (int p = 0; p < 4; p++) {
                int krow = kc * 16 + l7 + (quad & 1) * 8;
                int ncol = p * 16 + (quad >> 1) * 8;
                uint32_t r0, r1, r2, r3;
                ldsm4t(r0, r1, r2, r3, sVc + krow * TSTRB + ncol * 2);
                mma_f16(o[2*p],   ph[2*kc][0], ph[2*kc][1],
                        ph[2*kc+1][0], ph[2*kc+1][1], r0, r1);
                mma_f16(o[2*p+1], ph[2*kc][0], ph[2*kc][1],
                        ph[2*kc+1][0], ph[2*kc+1][1], r2, r3);
            }
        }
    }

    // Write ao (fp16 for gemm1)
    float inv0 = 1.f / l0, inv1 = 1.f / l1;
    int tok0 = b * SEQ + qt * 128 + warp * 16 + g;
#pragma unroll
    for (int ni = 0; ni < 8; ni++) {
        int col = h * HD + ni * 8 + 2 * tg;
        *(__half2*)&g_aoh[(size_t)tok0 * DIM + col] =
            __floats2half2_rn(o[ni][0] * inv0, o[ni][1] * inv0);
        *(__half2*)&g_aoh[(size_t)(tok0 + 8) * DIM + col] =
            __floats2half2_rn(o[ni][2] * inv1, o[ni][3] * inv1);
    }
}

// ===========================================================================
extern "C" void kernel_launch(void* const* d_in, const int* in_sizes, int n_in,
                              void* d_out, int out_size) {
    const float* x    = (const float*)d_in[0];
    const float* Wqkv = (const float*)d_in[1];
    const float* Wg   = (const float*)d_in[2];
    const float* Wout = (const float*)d_in[3];
    // d_in[4] = mask: all-true by construction, unused.
    float* out = (float*)d_out;

    cudaFuncSetAttribute(gemm_mma<0>, cudaFuncAttributeMaxDynamicSharedMemorySize, GEMM_SMEM);
    cudaFuncSetAttribute(gemm_mma<1>, cudaFuncAttributeMaxDynamicSharedMemorySize, GEMM_SMEM);
    cudaFuncSetAttribute(attn_tc, cudaFuncAttributeMaxDynamicSharedMemorySize, ATT_SMEM);

    cvt_all_kernel<<<4096, 256>>>(x, Wqkv, Wout);
    gates_kernel<<<NTOK, 128>>>(x, Wg);
    gemm_mma<0><<<dim3(QKVN / 128, NTOK / 128), 256, GEMM_SMEM>>>(QKVN, nullptr);
    attn_tc<<<dim3(SEQ / 128, NB * NH), 256, ATT_SMEM>>>();
    gemm_mma<1><<<dim3(OUTN / 128, NTOK / 128), 256, GEMM_SMEM>>>(OUTN, out);
}